// round 4
// baseline (speedup 1.0000x reference)
#include <cuda_runtime.h>
#include <cuda_bf16.h>
#include <cstdint>
#include <cstddef>

#define B_   512
#define T_   2048
#define NP   800          // C*M pairs
#define TPB  512
#define NBLK 128          // B_/4, 4 batches per block

#define L2E     1.4426950408889634f
#define TWO_L2E 2.8853900817779268f
#define SQ_L2E  1.2011224087864498f

// ---- shared layout (float offsets) ----
#define OFF_SQ   0        // Sq[4 quad][800][4] : S quads transposed, *2*log2e (12800 f)
#define OFF_AQ   12800    // Aq[4 quad][800][4] : A quads transposed           (12800 f)
#define OFF_UK   25600    // float2 uk[800]     : (U*sqrt(l2e), l2e*|S|^2)     ( 1600 f)
#define OFF_RED  27200    // float red[4][16][16]                              ( 1024 f)
#define OFF_ST   28224    // float st[4][20]                                   (   80 f)
#define OFF_GATE 28304    // float gate[2][4][8]                               (   64 f)
#define OFF_XB   28368    // float xb[2][4]                                    (    8 f)
#define SMEM_FLOATS 28376
#define SMEM_BYTES  (SMEM_FLOATS * 4)

typedef unsigned long long u64;

__device__ float g_gate[(size_t)B_ * T_ * 8];

__device__ __forceinline__ float ex2f(float a)
{
    float r;
    asm("ex2.approx.ftz.f32 %0, %1;" : "=f"(r) : "f"(a));
    return r;
}
__device__ __forceinline__ u64 fma2(u64 b, u64 c, u64 a)   // b*c + a
{
    u64 d;
    asm("fma.rn.f32x2 %0, %1, %2, %3;" : "=l"(d) : "l"(b), "l"(c), "l"(a));
    return d;
}
__device__ __forceinline__ u64 mul2(u64 a, u64 b)
{
    u64 d;
    asm("mul.rn.f32x2 %0, %1, %2;" : "=l"(d) : "l"(a), "l"(b));
    return d;
}
__device__ __forceinline__ u64 add2(u64 a, u64 b)
{
    u64 d;
    asm("add.rn.f32x2 %0, %1, %2;" : "=l"(d) : "l"(a), "l"(b));
    return d;
}
__device__ __forceinline__ float2 upk(u64 a)
{
    float2 f;
    asm("mov.b64 {%0, %1}, %2;" : "=f"(f.x), "=f"(f.y) : "l"(a));
    return f;
}
__device__ __forceinline__ u64 pk2(float lo, float hi)
{
    u64 d;
    asm("mov.b64 %0, {%1, %2};" : "=l"(d) : "f"(lo), "f"(hi));
    return d;
}
__device__ __forceinline__ u64 shfl64x(u64 v, int m)
{
    unsigned lo = (unsigned)v, hi = (unsigned)(v >> 32);
    lo = __shfl_xor_sync(0xffffffffu, lo, m);
    hi = __shfl_xor_sync(0xffffffffu, hi, m);
    return ((u64)hi << 32) | lo;
}

// ---------------------------------------------------------------------------
// Kernel 1: gate[b,t,:] = softmax(relu(x*W1+b1) @ W2 + b2). One thread per (b,t).
// ---------------------------------------------------------------------------
__global__ void gate_kernel(const float* __restrict__ x,
                            const float* __restrict__ W1,
                            const float* __restrict__ b1,
                            const float* __restrict__ W2,
                            const float* __restrict__ b2)
{
    int idx = blockIdx.x * blockDim.x + threadIdx.x;
    if (idx >= B_ * T_) return;
    float xv = x[idx];

    float lg[8];
#pragma unroll
    for (int c = 0; c < 8; c++) lg[c] = __ldg(&b2[c]);
#pragma unroll
    for (int jj = 0; jj < 16; jj++) {
        float h = fmaxf(fmaf(xv, __ldg(&W1[jj]), __ldg(&b1[jj])), 0.0f);
#pragma unroll
        for (int c = 0; c < 8; c++)
            lg[c] = fmaf(h, __ldg(&W2[jj * 8 + c]), lg[c]);
    }
    float m = lg[0];
#pragma unroll
    for (int c = 1; c < 8; c++) m = fmaxf(m, lg[c]);
    float e[8], ssum = 0.0f;
#pragma unroll
    for (int c = 0; c < 8; c++) { e[c] = __expf(lg[c] - m); ssum += e[c]; }
    float inv = 1.0f / ssum;
#pragma unroll
    for (int c = 0; c < 8; c++) g_gate[(size_t)idx * 8 + c] = e[c] * inv;
}

// ---------------------------------------------------------------------------
// Kernel 2: fused recurrent scan. 128 blocks x 512 threads, 4 batches/block.
// Thread (b = tid&3, pp = tid>>2) computes w_p and accumulates w_p*A[p][:]
// into a register-resident 16-dim accumulator; butterfly-reduce over pp.
// ---------------------------------------------------------------------------
__global__ void __launch_bounds__(TPB, 1)
scan_kernel(const float* __restrict__ x,
            const float* __restrict__ S,
            const float* __restrict__ U,
            const float* __restrict__ A,
            float* __restrict__ out)
{
    extern __shared__ float sm[];
    const int tid = threadIdx.x;
    const int b0  = blockIdx.x * 4;

    // ---------------- stage S', A (quad-transposed), (U', k) ----------------
    for (int idx = tid; idx < NP * 16; idx += TPB) {
        int p = idx >> 4, k = idx & 15;
        int slot = (k >> 2) * 3200 + (p << 2) + (k & 3);
        sm[OFF_SQ + slot] = TWO_L2E * S[idx];
        sm[OFF_AQ + slot] = A[idx];
    }
    for (int p = tid; p < NP; p += TPB) {
        float acc = 0.0f;
#pragma unroll
        for (int k = 0; k < 16; k++) { float v = S[p * 16 + k]; acc = fmaf(v, v, acc); }
        sm[OFF_UK + 2 * p]     = SQ_L2E * U[p];
        sm[OFF_UK + 2 * p + 1] = L2E * acc;
    }
    if (tid < 32) {
        sm[OFF_GATE + tid] = g_gate[((size_t)(b0 + (tid >> 3)) * T_) * 8 + (tid & 7)];
        if (tid < 4) sm[OFF_XB + tid] = SQ_L2E * x[(size_t)(b0 + tid) * T_];
    }
    __syncthreads();

    const int b    = tid & 3;
    const int pp   = tid >> 2;   // pair lane (0..127)
    const int lane = tid & 31;
    const int wrp  = tid >> 5;

    // precomputed cell index (p/100) for each unrolled iteration
    int cA[7];
#pragma unroll
    for (int i = 0; i < 6; i++) cA[i] = (unsigned)(pp + 128 * i) / 100u;
    cA[6] = (unsigned)(672 + pp) / 100u;       // valid only when pp >= 96

    // packed state (8 x f32x2), ss = l2e*|s|^2, xs = sqrt(l2e)*x_t
    u64 s0 = 0, s1 = 0, s2 = 0, s3 = 0, s4 = 0, s5 = 0, s6 = 0, s7 = 0;
    float ss = 0.0f;
    float xs = sm[OFF_XB + b];

    const ulonglong2* Sq2 = (const ulonglong2*)(sm + OFF_SQ);
    const ulonglong2* Aq2 = (const ulonglong2*)(sm + OFF_AQ);

    for (int t = 0; t < T_; t++) {
        const int par = t & 1;

        // next-step gate/x loads (committed after bar1, consumed after bar2)
        float gpre = 0.f, xpre = 0.f;
        const bool pf = (tid < 32) && (t + 1 < T_);
        if (pf) {
            gpre = g_gate[((size_t)(b0 + (tid >> 3)) * T_ + (t + 1)) * 8 + (tid & 7)];
            if (tid < 4) xpre = SQ_L2E * x[(size_t)(b0 + tid) * T_ + (t + 1)];
        }

        // ---------------- fused pair loop ----------------
        u64 a0 = 0, a1 = 0, a2 = 0, a3 = 0, a4 = 0, a5 = 0, a6 = 0, a7 = 0;
        const float* gsh = sm + OFF_GATE + par * 32 + b * 8;

        auto pairF = [&](int p, int ci) {
            ulonglong2 q0 = Sq2[p];
            ulonglong2 q1 = Sq2[800 + p];
            ulonglong2 q2 = Sq2[1600 + p];
            ulonglong2 q3 = Sq2[2400 + p];
            u64 da = mul2(q0.x, s0);
            da = fma2(q0.y, s1, da);
            da = fma2(q1.x, s2, da);
            da = fma2(q1.y, s3, da);
            u64 db = mul2(q2.x, s4);
            db = fma2(q2.y, s5, db);
            db = fma2(q3.x, s6, db);
            db = fma2(q3.y, s7, db);
            float2 fa = upk(da), fb = upk(db);
            float dot = (fa.x + fa.y) + (fb.x + fb.y);
            float2 uk = *(const float2*)(sm + OFF_UK + 2 * p);
            float du = xs - uk.x;
            float e  = (dot - ss) - fmaf(du, du, uk.y);
            float w  = gsh[ci] * ex2f(e);
            u64  w2  = pk2(w, w);
            ulonglong2 v0 = Aq2[p];
            ulonglong2 v1 = Aq2[800 + p];
            ulonglong2 v2 = Aq2[1600 + p];
            ulonglong2 v3 = Aq2[2400 + p];
            a0 = fma2(v0.x, w2, a0); a1 = fma2(v0.y, w2, a1);
            a2 = fma2(v1.x, w2, a2); a3 = fma2(v1.y, w2, a3);
            a4 = fma2(v2.x, w2, a4); a5 = fma2(v2.y, w2, a5);
            a6 = fma2(v3.x, w2, a6); a7 = fma2(v3.y, w2, a7);
        };
#pragma unroll
        for (int i = 0; i < 6; i++) pairF(pp + 128 * i, cA[i]);
        if (pp >= 96) pairF(672 + pp, cA[6]);   // tail pairs 768..799

        // ---------------- butterfly reduce over pp (b invariant) -------------
#pragma unroll
        for (int m = 4; m <= 16; m <<= 1) {
            a0 = add2(a0, shfl64x(a0, m));
            a1 = add2(a1, shfl64x(a1, m));
            a2 = add2(a2, shfl64x(a2, m));
            a3 = add2(a3, shfl64x(a3, m));
            a4 = add2(a4, shfl64x(a4, m));
            a5 = add2(a5, shfl64x(a5, m));
            a6 = add2(a6, shfl64x(a6, m));
            a7 = add2(a7, shfl64x(a7, m));
        }
        // holders: lanes 0-3 (b = lane). XOR-swizzled quad stores, conflict-free.
        if (lane < 4) {
            float4* dst = (float4*)(sm + OFF_RED) + (lane * 16 + wrp) * 4;
            float2 f0 = upk(a0), f1 = upk(a1), f2 = upk(a2), f3 = upk(a3);
            float2 f4 = upk(a4), f5 = upk(a5), f6 = upk(a6), f7 = upk(a7);
            float4 q[4];
            q[0] = make_float4(f0.x, f0.y, f1.x, f1.y);
            q[1] = make_float4(f2.x, f2.y, f3.x, f3.y);
            q[2] = make_float4(f4.x, f4.y, f5.x, f5.y);
            q[3] = make_float4(f6.x, f6.y, f7.x, f7.y);
#pragma unroll
            for (int i = 0; i < 4; i++) {
                int qq = i ^ lane;
                dst[qq] = q[qq];
            }
        }
        __syncthreads();                             // bar 1

        // commit prefetched gate/x for t+1 (parallel with final reduce)
        if (pf) {
            sm[OFF_GATE + (par ^ 1) * 32 + tid] = gpre;
            if (tid < 4) sm[OFF_XB + (par ^ 1) * 4 + tid] = xpre;
        }

        // ---------------- final reduce + output ----------------
        if (tid < 64) {
            const int bb = tid >> 4, nn = tid & 15;
            const float* r = sm + OFF_RED + bb * 256 + nn;
            float v = 0.0f;
#pragma unroll
            for (int w = 0; w < 16; w++) v += r[w * 16];
            sm[OFF_ST + bb * 20 + nn] = v;
            if (nn == 15) out[(size_t)(b0 + bb) * T_ + t] = v;
        }
        __syncthreads();                             // bar 2

        // reload packed state; recompute ss locally
        {
            const ulonglong2* st2 = (const ulonglong2*)(sm + OFF_ST + b * 20);
            ulonglong2 u0 = st2[0], u1 = st2[1], u2 = st2[2], u3 = st2[3];
            s0 = u0.x; s1 = u0.y; s2 = u1.x; s3 = u1.y;
            s4 = u2.x; s5 = u2.y; s6 = u3.x; s7 = u3.y;
            u64 acc = mul2(s0, s0);
            acc = fma2(s1, s1, acc);
            acc = fma2(s2, s2, acc);
            acc = fma2(s3, s3, acc);
            acc = fma2(s4, s4, acc);
            acc = fma2(s5, s5, acc);
            acc = fma2(s6, s6, acc);
            acc = fma2(s7, s7, acc);
            float2 fs = upk(acc);
            ss = L2E * (fs.x + fs.y);
            xs = sm[OFF_XB + (par ^ 1) * 4 + b];
        }
    }
}

// ---------------------------------------------------------------------------
extern "C" void kernel_launch(void* const* d_in, const int* in_sizes, int n_in,
                              void* d_out, int out_size)
{
    const float* x  = (const float*)d_in[0];
    const float* S  = (const float*)d_in[1];
    const float* U  = (const float*)d_in[2];
    const float* A  = (const float*)d_in[3];
    const float* W1 = (const float*)d_in[4];
    const float* b1 = (const float*)d_in[5];
    const float* W2 = (const float*)d_in[6];
    const float* b2 = (const float*)d_in[7];
    float* out = (float*)d_out;

    cudaFuncSetAttribute(scan_kernel,
                         cudaFuncAttributeMaxDynamicSharedMemorySize, SMEM_BYTES);

    gate_kernel<<<(B_ * T_ + 255) / 256, 256>>>(x, W1, b1, W2, b2);
    scan_kernel<<<NBLK, TPB, SMEM_BYTES>>>(x, S, U, A, out);
}

// round 5
// speedup vs baseline: 1.1348x; 1.1348x over previous
#include <cuda_runtime.h>
#include <cuda_bf16.h>
#include <cstdint>
#include <cstddef>

#define B_   512
#define T_   2048
#define NP   800          // C*M pairs
#define TPB  512
#define NBLK 128          // B_/4, 4 batches per block

#define L2E     1.4426950408889634f
#define TWO_L2E 2.8853900817779268f
#define SQ_L2E  1.2011224087864498f

// ---- shared layout (float offsets) ----
#define OFF_SQ   0        // Sq[4 quad][800][4] : S quads transposed, *2*log2e (12800 f)
#define OFF_AT   12800    // float at[16][804]  : A transposed, padded         (12864 f)
#define OFF_UK   25664    // float2 uk[800]     : (U*sqrt(l2e), l2e*|S|^2)     ( 1600 f)
#define OFF_W    27264    // float w[4][808]    : stride 808 -> conflict-free  ( 3232 f)
#define OFF_RED  30496    // float red[4][16][16]                              ( 1024 f)
#define OFF_ST   31520    // float st[4][20]                                   (   80 f)
#define OFF_GATE 31600    // float gate[2][4][8]                               (   64 f)
#define OFF_XB   31664    // float xb[2][4]                                    (    8 f)
#define SMEM_FLOATS 31672
#define SMEM_BYTES  (SMEM_FLOATS * 4)

typedef unsigned long long u64;

__device__ float g_gate[(size_t)B_ * T_ * 8];

__device__ __forceinline__ float ex2f(float a)
{
    float r;
    asm("ex2.approx.ftz.f32 %0, %1;" : "=f"(r) : "f"(a));
    return r;
}
__device__ __forceinline__ u64 fma2(u64 b, u64 c, u64 a)   // b*c + a
{
    u64 d;
    asm("fma.rn.f32x2 %0, %1, %2, %3;" : "=l"(d) : "l"(b), "l"(c), "l"(a));
    return d;
}
__device__ __forceinline__ u64 mul2(u64 a, u64 b)
{
    u64 d;
    asm("mul.rn.f32x2 %0, %1, %2;" : "=l"(d) : "l"(a), "l"(b));
    return d;
}
__device__ __forceinline__ float2 upk(u64 a)
{
    float2 f;
    asm("mov.b64 {%0, %1}, %2;" : "=f"(f.x), "=f"(f.y) : "l"(a));
    return f;
}

// ---------------------------------------------------------------------------
// Kernel 1: gate[b,t,:] = softmax(relu(x*W1+b1) @ W2 + b2). One thread per (b,t).
// ---------------------------------------------------------------------------
__global__ void gate_kernel(const float* __restrict__ x,
                            const float* __restrict__ W1,
                            const float* __restrict__ b1,
                            const float* __restrict__ W2,
                            const float* __restrict__ b2)
{
    int idx = blockIdx.x * blockDim.x + threadIdx.x;
    if (idx >= B_ * T_) return;
    float xv = x[idx];

    float lg[8];
#pragma unroll
    for (int c = 0; c < 8; c++) lg[c] = __ldg(&b2[c]);
#pragma unroll
    for (int jj = 0; jj < 16; jj++) {
        float h = fmaxf(fmaf(xv, __ldg(&W1[jj]), __ldg(&b1[jj])), 0.0f);
#pragma unroll
        for (int c = 0; c < 8; c++)
            lg[c] = fmaf(h, __ldg(&W2[jj * 8 + c]), lg[c]);
    }
    float m = lg[0];
#pragma unroll
    for (int c = 1; c < 8; c++) m = fmaxf(m, lg[c]);
    float e[8], ssum = 0.0f;
#pragma unroll
    for (int c = 0; c < 8; c++) { e[c] = __expf(lg[c] - m); ssum += e[c]; }
    float inv = 1.0f / ssum;
#pragma unroll
    for (int c = 0; c < 8; c++) g_gate[(size_t)idx * 8 + c] = e[c] * inv;
}

// ---------------------------------------------------------------------------
// Kernel 2: recurrent scan. 128 blocks x 512 threads, 4 batches per block.
// Phase A (b,pp) -> W in smem; Phase B (n,j) -> partials; 256-thread finish.
// Static smem loads are hoisted across barriers into the stall windows.
// ---------------------------------------------------------------------------
__global__ void __launch_bounds__(TPB, 1)
scan_kernel(const float* __restrict__ x,
            const float* __restrict__ S,
            const float* __restrict__ U,
            const float* __restrict__ A,
            float* __restrict__ out)
{
    extern __shared__ float sm[];
    const int tid = threadIdx.x;
    const int b0  = blockIdx.x * 4;

    // ---------------- stage S', A^T, (U', k) ----------------
    for (int idx = tid; idx < NP * 16; idx += TPB) {
        int p = idx >> 4, k = idx & 15;
        sm[OFF_SQ + (k >> 2) * 3200 + (p << 2) + (k & 3)] = TWO_L2E * S[idx];
        sm[OFF_AT + k * 804 + p] = A[idx];
    }
    for (int p = tid; p < NP; p += TPB) {
        float acc = 0.0f;
#pragma unroll
        for (int k = 0; k < 16; k++) { float v = S[p * 16 + k]; acc = fmaf(v, v, acc); }
        sm[OFF_UK + 2 * p]     = SQ_L2E * U[p];
        sm[OFF_UK + 2 * p + 1] = L2E * acc;
    }
    if (tid < 32) {
        sm[OFF_GATE + tid] = g_gate[((size_t)(b0 + (tid >> 3)) * T_) * 8 + (tid & 7)];
        if (tid < 4) sm[OFF_XB + tid] = SQ_L2E * x[(size_t)(b0 + tid) * T_];
    }
    __syncthreads();

    const int b    = tid & 3;    // phase A batch
    const int pp   = tid >> 2;   // phase A pair lane (0..127)
    const int nn   = tid & 15;   // phase B output dim
    const int j    = tid >> 4;   // phase B chunk lane (0..31)
    const int lane = tid & 31;
    const int wrp  = tid >> 5;

    // packed state (8 x f32x2), ss = l2e*|s|^2, xs = sqrt(l2e)*x_t
    u64 s0 = 0, s1 = 0, s2 = 0, s3 = 0, s4 = 0, s5 = 0, s6 = 0, s7 = 0;
    float ss = 0.0f;
    float xs = sm[OFF_XB + b];

    const ulonglong2* Sq2 = (const ulonglong2*)(sm + OFF_SQ);
    const ulonglong2* At2 = (const ulonglong2*)(sm + OFF_AT + nn * 804);
    const ulonglong2* Wb2 = (const ulonglong2*)(sm + OFF_W);

    // prefetched static data (survive across barriers; read-only smem)
    ulonglong2 pS0 = Sq2[pp];          // next phase-A iter0 q0

    for (int t = 0; t < T_; t++) {
        const int par = t & 1;

        // next-step gate/x loads (committed after bar1, consumed at step end)
        float gpre = 0.f, xpre = 0.f;
        const bool pf = (tid < 32) && (t + 1 < T_);
        if (pf) {
            gpre = g_gate[((size_t)(b0 + (tid >> 3)) * T_ + (t + 1)) * 8 + (tid & 7)];
            if (tid < 4) xpre = SQ_L2E * x[(size_t)(b0 + tid) * T_ + (t + 1)];
        }

        // ---------------- phase A: w[b][p] = gate * exp2(...) ----------------
        {
            const float* gsh  = sm + OFF_GATE + par * 32 + b * 8;
            float*       wrow = sm + OFF_W + b * 808;

            auto pairA = [&](int p, ulonglong2 q0, int ci) {
                ulonglong2 q1 = Sq2[800 + p];
                ulonglong2 q2 = Sq2[1600 + p];
                ulonglong2 q3 = Sq2[2400 + p];
                u64 da = mul2(q0.x, s0);
                da = fma2(q0.y, s1, da);
                da = fma2(q1.x, s2, da);
                da = fma2(q1.y, s3, da);
                u64 db = mul2(q2.x, s4);
                db = fma2(q2.y, s5, db);
                db = fma2(q3.x, s6, db);
                db = fma2(q3.y, s7, db);
                float2 fa = upk(da), fb = upk(db);
                float dot = (fa.x + fa.y) + (fb.x + fb.y);
                float2 uk = *(const float2*)(sm + OFF_UK + 2 * p);
                float du = xs - uk.x;
                float e  = (dot - ss) - fmaf(du, du, uk.y);
                wrow[p] = gsh[ci] * ex2f(e);
            };
            // iter 0 uses the pre-barrier-fetched q0
            pairA(pp, pS0, (unsigned)pp / 100u);
#pragma unroll
            for (int i = 1; i < 6; i++) {
                int p = pp + 128 * i;
                pairA(p, Sq2[p], (unsigned)p / 100u);
            }
            if (pp >= 96) pairA(672 + pp, Sq2[672 + pp], 7);   // pairs 768..799: cell 7
        }
        // prefetch phase-B A-chunks for iters 0-1 (static) into the bar1 window
        ulonglong2 pA0 = At2[j];
        ulonglong2 pA1 = At2[32 + j];
        __syncthreads();                             // bar 1

        // commit prefetched gate/x for t+1
        if (pf) {
            sm[OFF_GATE + (par ^ 1) * 32 + tid] = gpre;
            if (tid < 4) sm[OFF_XB + (par ^ 1) * 4 + tid] = xpre;
        }

        // ---------------- phase B: s_new[b][n] = sum_p w[b][p]*A[p][n] -------
        u64 c0 = 0, c1 = 0, c2 = 0, c3 = 0;
        auto chunkB = [&](int p4, ulonglong2 av) {
            ulonglong2 w0 = Wb2[p4];
            ulonglong2 w1 = Wb2[202 + p4];
            ulonglong2 w2 = Wb2[404 + p4];
            ulonglong2 w3 = Wb2[606 + p4];
            c0 = fma2(av.x, w0.x, c0); c0 = fma2(av.y, w0.y, c0);
            c1 = fma2(av.x, w1.x, c1); c1 = fma2(av.y, w1.y, c1);
            c2 = fma2(av.x, w2.x, c2); c2 = fma2(av.y, w2.y, c2);
            c3 = fma2(av.x, w3.x, c3); c3 = fma2(av.y, w3.y, c3);
        };
        chunkB(j, pA0);                              // prefetched
        chunkB(32 + j, pA1);                         // prefetched
#pragma unroll
        for (int i = 2; i < 6; i++) { int p4 = j + 32 * i; chunkB(p4, At2[p4]); }
        if (j >= 24) chunkB(168 + j, At2[168 + j]);  // tail chunks 192..199

        // prefetch next step's phase-A iter0 q0 into the bar2/bar3 window
        pS0 = Sq2[pp];

        float2 f0 = upk(c0), f1 = upk(c1), f2 = upk(c2), f3 = upk(c3);
        float a0 = f0.x + f0.y, a1 = f1.x + f1.y, a2 = f2.x + f2.y, a3 = f3.x + f3.y;
        a0 += __shfl_xor_sync(0xffffffffu, a0, 16);
        a1 += __shfl_xor_sync(0xffffffffu, a1, 16);
        a2 += __shfl_xor_sync(0xffffffffu, a2, 16);
        a3 += __shfl_xor_sync(0xffffffffu, a3, 16);
        if (lane < 16) {
            sm[OFF_RED +       wrp * 16 + lane] = a0;
            sm[OFF_RED + 256 + wrp * 16 + lane] = a1;
            sm[OFF_RED + 512 + wrp * 16 + lane] = a2;
            sm[OFF_RED + 768 + wrp * 16 + lane] = a3;
        }
        __syncthreads();                             // bar 2

        // ---------------- final reduce + output (256 threads, 4+shfl) --------
        if (tid < 256) {
            const int bb = tid >> 6, n2 = (tid >> 2) & 15, g = tid & 3;
            const float* r = sm + OFF_RED + bb * 256 + g * 16 + n2;
            float v = (r[0] + r[64]) + (r[128] + r[192]);   // warps g, g+4, g+8, g+12
            v += __shfl_xor_sync(0xffffffffu, v, 1);
            v += __shfl_xor_sync(0xffffffffu, v, 2);
            if (g == 0) {
                sm[OFF_ST + bb * 20 + n2] = v;
                if (n2 == 15) out[(size_t)(b0 + bb) * T_ + t] = v;
            }
        }
        __syncthreads();                             // bar 3

        // reload packed state; recompute ss locally
        {
            const ulonglong2* st2 = (const ulonglong2*)(sm + OFF_ST + b * 20);
            ulonglong2 u0 = st2[0], u1 = st2[1], u2 = st2[2], u3 = st2[3];
            s0 = u0.x; s1 = u0.y; s2 = u1.x; s3 = u1.y;
            s4 = u2.x; s5 = u2.y; s6 = u3.x; s7 = u3.y;
            u64 acc = mul2(s0, s0);
            acc = fma2(s1, s1, acc);
            acc = fma2(s2, s2, acc);
            acc = fma2(s3, s3, acc);
            acc = fma2(s4, s4, acc);
            acc = fma2(s5, s5, acc);
            acc = fma2(s6, s6, acc);
            acc = fma2(s7, s7, acc);
            float2 fs = upk(acc);
            ss = L2E * (fs.x + fs.y);
            xs = sm[OFF_XB + (par ^ 1) * 4 + b];
        }
    }
}

// ---------------------------------------------------------------------------
extern "C" void kernel_launch(void* const* d_in, const int* in_sizes, int n_in,
                              void* d_out, int out_size)
{
    const float* x  = (const float*)d_in[0];
    const float* S  = (const float*)d_in[1];
    const float* U  = (const float*)d_in[2];
    const float* A  = (const float*)d_in[3];
    const float* W1 = (const float*)d_in[4];
    const float* b1 = (const float*)d_in[5];
    const float* W2 = (const float*)d_in[6];
    const float* b2 = (const float*)d_in[7];
    float* out = (float*)d_out;

    cudaFuncSetAttribute(scan_kernel,
                         cudaFuncAttributeMaxDynamicSharedMemorySize, SMEM_BYTES);

    gate_kernel<<<(B_ * T_ + 255) / 256, 256>>>(x, W1, b1, W2, b2);
    scan_kernel<<<NBLK, TPB, SMEM_BYTES>>>(x, S, U, A, out);
}

// round 6
// speedup vs baseline: 1.2270x; 1.0813x over previous
#include <cuda_runtime.h>
#include <cuda_bf16.h>
#include <cstdint>
#include <cstddef>

#define B_   512
#define T_   2048
#define NP   800          // C*M pairs
#define TPB  512
#define NBLK 128          // B_/4, 4 batches per block

#define L2E     1.4426950408889634f
#define TWO_L2E 2.8853900817779268f
#define SQ_L2E  1.2011224087864498f

// ---- shared layout (float offsets) ----
#define OFF_SQ   0        // Sq[4 quad][800][4] : S quads transposed, *2*log2e (12800 f)
#define OFF_AT   12800    // float at[16][804]  : A transposed, padded         (12864 f)
#define OFF_UK   25664    // float2 uk[800]     : (U*sqrt(l2e), l2e*|S|^2)     ( 1600 f)
#define OFF_W    27264    // float w[4][808]    : stride 808 -> conflict-free  ( 3232 f)
#define OFF_RED  30496    // float red[4][16][16]                              ( 1024 f)
#define OFF_ST   31520    // float st[4][20]                                   (   80 f)
#define OFF_GATE 31600    // float gate[2][4][8]                               (   64 f)
#define OFF_XB   31664    // float xb[2][4]                                    (    8 f)
#define SMEM_FLOATS 31672
#define SMEM_BYTES  (SMEM_FLOATS * 4)

typedef unsigned long long u64;

__device__ float g_gate[(size_t)B_ * T_ * 8];

__device__ __forceinline__ float ex2f(float a)
{
    float r;
    asm("ex2.approx.ftz.f32 %0, %1;" : "=f"(r) : "f"(a));
    return r;
}
__device__ __forceinline__ u64 fma2(u64 b, u64 c, u64 a)   // b*c + a
{
    u64 d;
    asm("fma.rn.f32x2 %0, %1, %2, %3;" : "=l"(d) : "l"(b), "l"(c), "l"(a));
    return d;
}
__device__ __forceinline__ u64 mul2(u64 a, u64 b)
{
    u64 d;
    asm("mul.rn.f32x2 %0, %1, %2;" : "=l"(d) : "l"(a), "l"(b));
    return d;
}
__device__ __forceinline__ float2 upk(u64 a)
{
    float2 f;
    asm("mov.b64 {%0, %1}, %2;" : "=f"(f.x), "=f"(f.y) : "l"(a));
    return f;
}

// ---------------------------------------------------------------------------
// Kernel 1: gate[b,t,:] = softmax(relu(x*W1+b1) @ W2 + b2). One thread per (b,t).
// ---------------------------------------------------------------------------
__global__ void gate_kernel(const float* __restrict__ x,
                            const float* __restrict__ W1,
                            const float* __restrict__ b1,
                            const float* __restrict__ W2,
                            const float* __restrict__ b2)
{
    int idx = blockIdx.x * blockDim.x + threadIdx.x;
    if (idx >= B_ * T_) return;
    float xv = x[idx];

    float lg[8];
#pragma unroll
    for (int c = 0; c < 8; c++) lg[c] = __ldg(&b2[c]);
#pragma unroll
    for (int jj = 0; jj < 16; jj++) {
        float h = fmaxf(fmaf(xv, __ldg(&W1[jj]), __ldg(&b1[jj])), 0.0f);
#pragma unroll
        for (int c = 0; c < 8; c++)
            lg[c] = fmaf(h, __ldg(&W2[jj * 8 + c]), lg[c]);
    }
    float m = lg[0];
#pragma unroll
    for (int c = 1; c < 8; c++) m = fmaxf(m, lg[c]);
    float e[8], ssum = 0.0f;
#pragma unroll
    for (int c = 0; c < 8; c++) { e[c] = __expf(lg[c] - m); ssum += e[c]; }
    float inv = 1.0f / ssum;
#pragma unroll
    for (int c = 0; c < 8; c++) g_gate[(size_t)idx * 8 + c] = e[c] * inv;
}

// ---------------------------------------------------------------------------
// Kernel 2: recurrent scan. 128 blocks x 512 threads, 4 batches per block.
// Phase A (b,pp) -> W in smem; Phase B (n,j) with A register-cached;
// 256-thread final reduce. A is static: 6 chunks/thread live in registers
// for all 2048 steps, eliminating 400 LDS wavefronts per block-step.
// ---------------------------------------------------------------------------
__global__ void __launch_bounds__(TPB, 1)
scan_kernel(const float* __restrict__ x,
            const float* __restrict__ S,
            const float* __restrict__ U,
            const float* __restrict__ A,
            float* __restrict__ out)
{
    extern __shared__ float sm[];
    const int tid = threadIdx.x;
    const int b0  = blockIdx.x * 4;

    // ---------------- stage S', A^T, (U', k) ----------------
    for (int idx = tid; idx < NP * 16; idx += TPB) {
        int p = idx >> 4, k = idx & 15;
        sm[OFF_SQ + (k >> 2) * 3200 + (p << 2) + (k & 3)] = TWO_L2E * S[idx];
        sm[OFF_AT + k * 804 + p] = A[idx];
    }
    for (int p = tid; p < NP; p += TPB) {
        float acc = 0.0f;
#pragma unroll
        for (int k = 0; k < 16; k++) { float v = S[p * 16 + k]; acc = fmaf(v, v, acc); }
        sm[OFF_UK + 2 * p]     = SQ_L2E * U[p];
        sm[OFF_UK + 2 * p + 1] = L2E * acc;
    }
    if (tid < 32) {
        sm[OFF_GATE + tid] = g_gate[((size_t)(b0 + (tid >> 3)) * T_) * 8 + (tid & 7)];
        if (tid < 4) sm[OFF_XB + tid] = SQ_L2E * x[(size_t)(b0 + tid) * T_];
    }
    __syncthreads();

    const int b    = tid & 3;    // phase A batch
    const int pp   = tid >> 2;   // phase A pair lane (0..127)
    const int nn   = tid & 15;   // phase B output dim
    const int j    = tid >> 4;   // phase B chunk lane (0..31)
    const int lane = tid & 31;
    const int wrp  = tid >> 5;

    const ulonglong2* Sq2 = (const ulonglong2*)(sm + OFF_SQ);
    const ulonglong2* At2 = (const ulonglong2*)(sm + OFF_AT + nn * 804);
    const ulonglong2* Wb2 = (const ulonglong2*)(sm + OFF_W);

    // -------- A register cache: 6 chunks per thread, static across t --------
    ulonglong2 Ac[6];
#pragma unroll
    for (int i = 0; i < 6; i++) Ac[i] = At2[j + 32 * i];

    // packed state (8 x f32x2), ss = l2e*|s|^2, xs = sqrt(l2e)*x_t
    u64 s0 = 0, s1 = 0, s2 = 0, s3 = 0, s4 = 0, s5 = 0, s6 = 0, s7 = 0;
    float ss = 0.0f;
    float xs = sm[OFF_XB + b];

    for (int t = 0; t < T_; t++) {
        const int par = t & 1;

        // next-step gate/x loads (committed after bar1, consumed at step end)
        float gpre = 0.f, xpre = 0.f;
        const bool pf = (tid < 32) && (t + 1 < T_);
        if (pf) {
            gpre = g_gate[((size_t)(b0 + (tid >> 3)) * T_ + (t + 1)) * 8 + (tid & 7)];
            if (tid < 4) xpre = SQ_L2E * x[(size_t)(b0 + tid) * T_ + (t + 1)];
        }

        // ---------------- phase A: w[b][p] = gate * exp2(...) ----------------
        {
            const float* gsh  = sm + OFF_GATE + par * 32 + b * 8;
            float*       wrow = sm + OFF_W + b * 808;

            auto pairA = [&](int p, int ci) {
                ulonglong2 q0 = Sq2[p];
                ulonglong2 q1 = Sq2[800 + p];
                ulonglong2 q2 = Sq2[1600 + p];
                ulonglong2 q3 = Sq2[2400 + p];
                u64 da = mul2(q0.x, s0);
                da = fma2(q0.y, s1, da);
                da = fma2(q1.x, s2, da);
                da = fma2(q1.y, s3, da);
                u64 db = mul2(q2.x, s4);
                db = fma2(q2.y, s5, db);
                db = fma2(q3.x, s6, db);
                db = fma2(q3.y, s7, db);
                float2 fa = upk(da), fb = upk(db);
                float dot = (fa.x + fa.y) + (fb.x + fb.y);
                float2 uk = *(const float2*)(sm + OFF_UK + 2 * p);
                float du = xs - uk.x;
                float e  = (dot - ss) - fmaf(du, du, uk.y);
                wrow[p] = gsh[ci] * ex2f(e);
            };
#pragma unroll
            for (int i = 0; i < 6; i++) {
                int p = pp + 128 * i;
                pairA(p, (unsigned)p / 100u);
            }
            if (pp >= 96) pairA(672 + pp, 7);   // pairs 768..799: cell 7
        }
        __syncthreads();                             // bar 1

        // commit prefetched gate/x for t+1
        if (pf) {
            sm[OFF_GATE + (par ^ 1) * 32 + tid] = gpre;
            if (tid < 4) sm[OFF_XB + (par ^ 1) * 4 + tid] = xpre;
        }

        // ---------------- phase B: s_new[b][n] = sum_p w[b][p]*A[p][n] -------
        u64 c0 = 0, c1 = 0, c2 = 0, c3 = 0;
        auto chunkB = [&](int p4, ulonglong2 av) {
            ulonglong2 w0 = Wb2[p4];
            ulonglong2 w1 = Wb2[202 + p4];
            ulonglong2 w2 = Wb2[404 + p4];
            ulonglong2 w3 = Wb2[606 + p4];
            c0 = fma2(av.x, w0.x, c0); c0 = fma2(av.y, w0.y, c0);
            c1 = fma2(av.x, w1.x, c1); c1 = fma2(av.y, w1.y, c1);
            c2 = fma2(av.x, w2.x, c2); c2 = fma2(av.y, w2.y, c2);
            c3 = fma2(av.x, w3.x, c3); c3 = fma2(av.y, w3.y, c3);
        };
#pragma unroll
        for (int i = 0; i < 6; i++) chunkB(j + 32 * i, Ac[i]);
        if (j >= 24) chunkB(168 + j, At2[168 + j]);  // tail chunks 192..199

        float2 f0 = upk(c0), f1 = upk(c1), f2 = upk(c2), f3 = upk(c3);
        float a0 = f0.x + f0.y, a1 = f1.x + f1.y, a2 = f2.x + f2.y, a3 = f3.x + f3.y;
        a0 += __shfl_xor_sync(0xffffffffu, a0, 16);
        a1 += __shfl_xor_sync(0xffffffffu, a1, 16);
        a2 += __shfl_xor_sync(0xffffffffu, a2, 16);
        a3 += __shfl_xor_sync(0xffffffffu, a3, 16);
        if (lane < 16) {
            sm[OFF_RED +       wrp * 16 + lane] = a0;
            sm[OFF_RED + 256 + wrp * 16 + lane] = a1;
            sm[OFF_RED + 512 + wrp * 16 + lane] = a2;
            sm[OFF_RED + 768 + wrp * 16 + lane] = a3;
        }
        __syncthreads();                             // bar 2

        // ---------------- final reduce + output (256 threads, 4+shfl) --------
        if (tid < 256) {
            const int bb = tid >> 6, n2 = (tid >> 2) & 15, g = tid & 3;
            const float* r = sm + OFF_RED + bb * 256 + g * 16 + n2;
            float v = (r[0] + r[64]) + (r[128] + r[192]);   // warps g, g+4, g+8, g+12
            v += __shfl_xor_sync(0xffffffffu, v, 1);
            v += __shfl_xor_sync(0xffffffffu, v, 2);
            if (g == 0) {
                sm[OFF_ST + bb * 20 + n2] = v;
                if (n2 == 15) out[(size_t)(b0 + bb) * T_ + t] = v;
            }
        }
        __syncthreads();                             // bar 3

        // reload packed state; recompute ss locally
        {
            const ulonglong2* st2 = (const ulonglong2*)(sm + OFF_ST + b * 20);
            ulonglong2 u0 = st2[0], u1 = st2[1], u2 = st2[2], u3 = st2[3];
            s0 = u0.x; s1 = u0.y; s2 = u1.x; s3 = u1.y;
            s4 = u2.x; s5 = u2.y; s6 = u3.x; s7 = u3.y;
            u64 acc = mul2(s0, s0);
            acc = fma2(s1, s1, acc);
            acc = fma2(s2, s2, acc);
            acc = fma2(s3, s3, acc);
            acc = fma2(s4, s4, acc);
            acc = fma2(s5, s5, acc);
            acc = fma2(s6, s6, acc);
            acc = fma2(s7, s7, acc);
            float2 fs = upk(acc);
            ss = L2E * (fs.x + fs.y);
            xs = sm[OFF_XB + (par ^ 1) * 4 + b];
        }
    }
}

// ---------------------------------------------------------------------------
extern "C" void kernel_launch(void* const* d_in, const int* in_sizes, int n_in,
                              void* d_out, int out_size)
{
    const float* x  = (const float*)d_in[0];
    const float* S  = (const float*)d_in[1];
    const float* U  = (const float*)d_in[2];
    const float* A  = (const float*)d_in[3];
    const float* W1 = (const float*)d_in[4];
    const float* b1 = (const float*)d_in[5];
    const float* W2 = (const float*)d_in[6];
    const float* b2 = (const float*)d_in[7];
    float* out = (float*)d_out;

    cudaFuncSetAttribute(scan_kernel,
                         cudaFuncAttributeMaxDynamicSharedMemorySize, SMEM_BYTES);

    gate_kernel<<<(B_ * T_ + 255) / 256, 256>>>(x, W1, b1, W2, b2);
    scan_kernel<<<NBLK, TPB, SMEM_BYTES>>>(x, S, U, A, out);
}

// round 7
// speedup vs baseline: 1.3397x; 1.0918x over previous
#include <cuda_runtime.h>
#include <cuda_bf16.h>
#include <cstdint>
#include <cstddef>

#define B_   512
#define T_   2048
#define NP   800          // C*M pairs
#define TPB  512
#define NBLK 128          // B_/4, 4 batches per block

#define L2E     1.4426950408889634f
#define TWO_L2E 2.8853900817779268f

// ---- shared layout (float offsets) ----
#define OFF_SQ   0        // Sq[4 quad][800][4] : S quads transposed, *2*log2e (12800 f)
#define OFF_AT   12800    // float at[16][804]  : A transposed, padded         (12864 f)
#define OFF_UK   25664    // float2 uk[800]     : (2*l2e*U, l2e*(|S|^2+U^2))   ( 1600 f)
#define OFF_W    27264    // float w[4][808]    : stride 808 -> conflict-free  ( 3232 f)
#define OFF_RED  30496    // float red[4][16][16]                              ( 1024 f)
#define OFF_ST   31520    // float st[4][20]                                   (   80 f)
#define OFF_GATE 31600    // float gate[2][4][8]                               (   64 f)
#define OFF_XB   31664    // float xb[2][4]                                    (    8 f)
#define SMEM_FLOATS 31672
#define SMEM_BYTES  (SMEM_FLOATS * 4)

typedef unsigned long long u64;

__device__ float g_gate[(size_t)B_ * T_ * 8];

__device__ __forceinline__ float ex2f(float a)
{
    float r;
    asm("ex2.approx.ftz.f32 %0, %1;" : "=f"(r) : "f"(a));
    return r;
}
__device__ __forceinline__ u64 fma2(u64 b, u64 c, u64 a)   // b*c + a
{
    u64 d;
    asm("fma.rn.f32x2 %0, %1, %2, %3;" : "=l"(d) : "l"(b), "l"(c), "l"(a));
    return d;
}
__device__ __forceinline__ u64 mul2(u64 a, u64 b)
{
    u64 d;
    asm("mul.rn.f32x2 %0, %1, %2;" : "=l"(d) : "l"(a), "l"(b));
    return d;
}
__device__ __forceinline__ float2 upk(u64 a)
{
    float2 f;
    asm("mov.b64 {%0, %1}, %2;" : "=f"(f.x), "=f"(f.y) : "l"(a));
    return f;
}
__device__ __forceinline__ u64 pk2(float lo, float hi)
{
    u64 d;
    asm("mov.b64 %0, {%1, %2};" : "=l"(d) : "f"(lo), "f"(hi));
    return d;
}

// ---------------------------------------------------------------------------
// Kernel 1: gate[b,t,:] = softmax(relu(x*W1+b1) @ W2 + b2). One thread per (b,t).
// ---------------------------------------------------------------------------
__global__ void gate_kernel(const float* __restrict__ x,
                            const float* __restrict__ W1,
                            const float* __restrict__ b1,
                            const float* __restrict__ W2,
                            const float* __restrict__ b2)
{
    int idx = blockIdx.x * blockDim.x + threadIdx.x;
    if (idx >= B_ * T_) return;
    float xv = x[idx];

    float lg[8];
#pragma unroll
    for (int c = 0; c < 8; c++) lg[c] = __ldg(&b2[c]);
#pragma unroll
    for (int jj = 0; jj < 16; jj++) {
        float h = fmaxf(fmaf(xv, __ldg(&W1[jj]), __ldg(&b1[jj])), 0.0f);
#pragma unroll
        for (int c = 0; c < 8; c++)
            lg[c] = fmaf(h, __ldg(&W2[jj * 8 + c]), lg[c]);
    }
    float m = lg[0];
#pragma unroll
    for (int c = 1; c < 8; c++) m = fmaxf(m, lg[c]);
    float e[8], ssum = 0.0f;
#pragma unroll
    for (int c = 0; c < 8; c++) { e[c] = __expf(lg[c] - m); ssum += e[c]; }
    float inv = 1.0f / ssum;
#pragma unroll
    for (int c = 0; c < 8; c++) g_gate[(size_t)idx * 8 + c] = e[c] * inv;
}

// ---------------------------------------------------------------------------
// Kernel 2: recurrent scan. 128 blocks x 512 threads, 4 batches per block.
// Phase A (b,pp) processes double-pairs (2dp,2dp+1): shared uk LDS.128,
// shared gate LDS.32, one STS.64. Exponent: log2(phi*?) = dot(+seed -h')
// + x*u2[p] - k'[p], h' = l2e*(|s|^2+x^2) folded into the dot seed.
// Phase B (nn,j) with A register-cached. 256-thread final reduce.
// ---------------------------------------------------------------------------
__global__ void __launch_bounds__(TPB, 1)
scan_kernel(const float* __restrict__ x,
            const float* __restrict__ S,
            const float* __restrict__ U,
            const float* __restrict__ A,
            float* __restrict__ out)
{
    extern __shared__ float sm[];
    const int tid = threadIdx.x;
    const int b0  = blockIdx.x * 4;

    // ---------------- stage S', A^T, (u2, k') ----------------
    for (int idx = tid; idx < NP * 16; idx += TPB) {
        int p = idx >> 4, k = idx & 15;
        sm[OFF_SQ + (k >> 2) * 3200 + (p << 2) + (k & 3)] = TWO_L2E * S[idx];
        sm[OFF_AT + k * 804 + p] = A[idx];
    }
    for (int p = tid; p < NP; p += TPB) {
        float acc = 0.0f;
#pragma unroll
        for (int k = 0; k < 16; k++) { float v = S[p * 16 + k]; acc = fmaf(v, v, acc); }
        float uv = U[p];
        sm[OFF_UK + 2 * p]     = TWO_L2E * uv;
        sm[OFF_UK + 2 * p + 1] = L2E * fmaf(uv, uv, acc);
    }
    if (tid < 32) {
        sm[OFF_GATE + tid] = g_gate[((size_t)(b0 + (tid >> 3)) * T_) * 8 + (tid & 7)];
        if (tid < 4) sm[OFF_XB + tid] = x[(size_t)(b0 + tid) * T_];
    }
    __syncthreads();

    const int b    = tid & 3;    // phase A batch
    const int pp   = tid >> 2;   // phase A double-pair lane (0..127)
    const int nn   = tid & 15;   // phase B output dim
    const int j    = tid >> 4;   // phase B chunk lane (0..31)
    const int lane = tid & 31;
    const int wrp  = tid >> 5;

    const ulonglong2* Sq2 = (const ulonglong2*)(sm + OFF_SQ);
    const ulonglong2* At2 = (const ulonglong2*)(sm + OFF_AT + nn * 804);
    const ulonglong2* Wb2 = (const ulonglong2*)(sm + OFF_W);

    // -------- A register cache: 6 chunks per thread, static across t --------
    ulonglong2 Ac[6];
#pragma unroll
    for (int i = 0; i < 6; i++) Ac[i] = At2[j + 32 * i];

    // packed state (8 x f32x2); xv = raw x_t; hs = (-h', 0) dot seed
    u64 s0 = 0, s1 = 0, s2 = 0, s3 = 0, s4 = 0, s5 = 0, s6 = 0, s7 = 0;
    float xv = sm[OFF_XB + b];
    u64 hs = pk2(-L2E * xv * xv, 0.0f);

    for (int t = 0; t < T_; t++) {
        const int par = t & 1;

        // next-step gate/x loads (committed after bar1, consumed at step end)
        float gpre = 0.f, xpre = 0.f;
        const bool pf = (tid < 32) && (t + 1 < T_);
        if (pf) {
            gpre = g_gate[((size_t)(b0 + (tid >> 3)) * T_ + (t + 1)) * 8 + (tid & 7)];
            if (tid < 4) xpre = x[(size_t)(b0 + tid) * T_ + (t + 1)];
        }

        // ---------------- phase A: w[b][2dp..2dp+1] ----------------
        {
            const float* gsh = sm + OFF_GATE + par * 32 + b * 8;

            auto dpair = [&](int dp, int ci) {
                const int p0 = 2 * dp;
                ulonglong2 q0a = Sq2[p0],        q0b = Sq2[p0 + 1];
                ulonglong2 q1a = Sq2[800 + p0],  q1b = Sq2[801 + p0];
                ulonglong2 q2a = Sq2[1600 + p0], q2b = Sq2[1601 + p0];
                ulonglong2 q3a = Sq2[2400 + p0], q3b = Sq2[2401 + p0];
                float4 uk4 = *(const float4*)(sm + OFF_UK + 4 * dp);
                float g = gsh[ci];

                u64 da = fma2(q0a.x, s0, hs);
                da = fma2(q0a.y, s1, da);
                da = fma2(q1a.x, s2, da);
                da = fma2(q1a.y, s3, da);
                u64 db = mul2(q2a.x, s4);
                db = fma2(q2a.y, s5, db);
                db = fma2(q3a.x, s6, db);
                db = fma2(q3a.y, s7, db);
                float2 fa = upk(da), fb = upk(db);
                float e0 = fmaf(xv, uk4.x, (fa.x + fa.y) + (fb.x + fb.y)) - uk4.y;

                u64 dc = fma2(q0b.x, s0, hs);
                dc = fma2(q0b.y, s1, dc);
                dc = fma2(q1b.x, s2, dc);
                dc = fma2(q1b.y, s3, dc);
                u64 dd = mul2(q2b.x, s4);
                dd = fma2(q2b.y, s5, dd);
                dd = fma2(q3b.x, s6, dd);
                dd = fma2(q3b.y, s7, dd);
                float2 fc = upk(dc), fd = upk(dd);
                float e1 = fmaf(xv, uk4.z, (fc.x + fc.y) + (fd.x + fd.y)) - uk4.w;

                *(float2*)(sm + OFF_W + b * 808 + p0) =
                    make_float2(g * ex2f(e0), g * ex2f(e1));
            };
#pragma unroll
            for (int i = 0; i < 3; i++) {
                int dp = pp + 128 * i;
                dpair(dp, (unsigned)dp / 50u);
            }
            if (pp >= 112) dpair(272 + pp, 7);   // dp 384..399 -> pairs 768..799
        }
        __syncthreads();                             // bar 1

        // commit prefetched gate/x for t+1
        if (pf) {
            sm[OFF_GATE + (par ^ 1) * 32 + tid] = gpre;
            if (tid < 4) sm[OFF_XB + (par ^ 1) * 4 + tid] = xpre;
        }

        // ---------------- phase B: s_new[b][n] = sum_p w[b][p]*A[p][n] -------
        u64 c0 = 0, c1 = 0, c2 = 0, c3 = 0;
        auto chunkB = [&](int p4, ulonglong2 av) {
            ulonglong2 w0 = Wb2[p4];
            ulonglong2 w1 = Wb2[202 + p4];
            ulonglong2 w2 = Wb2[404 + p4];
            ulonglong2 w3 = Wb2[606 + p4];
            c0 = fma2(av.x, w0.x, c0); c0 = fma2(av.y, w0.y, c0);
            c1 = fma2(av.x, w1.x, c1); c1 = fma2(av.y, w1.y, c1);
            c2 = fma2(av.x, w2.x, c2); c2 = fma2(av.y, w2.y, c2);
            c3 = fma2(av.x, w3.x, c3); c3 = fma2(av.y, w3.y, c3);
        };
#pragma unroll
        for (int i = 0; i < 6; i++) chunkB(j + 32 * i, Ac[i]);
        if (j >= 24) chunkB(168 + j, At2[168 + j]);  // tail chunks 192..199

        float2 f0 = upk(c0), f1 = upk(c1), f2 = upk(c2), f3 = upk(c3);
        float a0 = f0.x + f0.y, a1 = f1.x + f1.y, a2 = f2.x + f2.y, a3 = f3.x + f3.y;
        a0 += __shfl_xor_sync(0xffffffffu, a0, 16);
        a1 += __shfl_xor_sync(0xffffffffu, a1, 16);
        a2 += __shfl_xor_sync(0xffffffffu, a2, 16);
        a3 += __shfl_xor_sync(0xffffffffu, a3, 16);
        if (lane < 16) {
            sm[OFF_RED +       wrp * 16 + lane] = a0;
            sm[OFF_RED + 256 + wrp * 16 + lane] = a1;
            sm[OFF_RED + 512 + wrp * 16 + lane] = a2;
            sm[OFF_RED + 768 + wrp * 16 + lane] = a3;
        }
        __syncthreads();                             // bar 2

        // ---------------- final reduce + output (256 threads, 4+shfl) --------
        if (tid < 256) {
            const int bb = tid >> 6, n2 = (tid >> 2) & 15, g = tid & 3;
            const float* r = sm + OFF_RED + bb * 256 + g * 16 + n2;
            float v = (r[0] + r[64]) + (r[128] + r[192]);   // warps g, g+4, g+8, g+12
            v += __shfl_xor_sync(0xffffffffu, v, 1);
            v += __shfl_xor_sync(0xffffffffu, v, 2);
            if (g == 0) {
                sm[OFF_ST + bb * 20 + n2] = v;
                if (n2 == 15) out[(size_t)(b0 + bb) * T_ + t] = v;
            }
        }
        __syncthreads();                             // bar 3

        // reload packed state; recompute h' locally
        {
            const ulonglong2* st2 = (const ulonglong2*)(sm + OFF_ST + b * 20);
            ulonglong2 u0 = st2[0], u1 = st2[1], u2 = st2[2], u3 = st2[3];
            s0 = u0.x; s1 = u0.y; s2 = u1.x; s3 = u1.y;
            s4 = u2.x; s5 = u2.y; s6 = u3.x; s7 = u3.y;
            xv = sm[OFF_XB + (par ^ 1) * 4 + b];
            u64 acc = mul2(s0, s0);
            acc = fma2(s1, s1, acc);
            acc = fma2(s2, s2, acc);
            acc = fma2(s3, s3, acc);
            acc = fma2(s4, s4, acc);
            acc = fma2(s5, s5, acc);
            acc = fma2(s6, s6, acc);
            acc = fma2(s7, s7, acc);
            float2 fs = upk(acc);
            float hv = fmaf(xv, xv, fs.x + fs.y);
            hs = pk2(-L2E * hv, 0.0f);
        }
    }
}

// ---------------------------------------------------------------------------
extern "C" void kernel_launch(void* const* d_in, const int* in_sizes, int n_in,
                              void* d_out, int out_size)
{
    const float* x  = (const float*)d_in[0];
    const float* S  = (const float*)d_in[1];
    const float* U  = (const float*)d_in[2];
    const float* A  = (const float*)d_in[3];
    const float* W1 = (const float*)d_in[4];
    const float* b1 = (const float*)d_in[5];
    const float* W2 = (const float*)d_in[6];
    const float* b2 = (const float*)d_in[7];
    float* out = (float*)d_out;

    cudaFuncSetAttribute(scan_kernel,
                         cudaFuncAttributeMaxDynamicSharedMemorySize, SMEM_BYTES);

    gate_kernel<<<(B_ * T_ + 255) / 256, 256>>>(x, W1, b1, W2, b2);
    scan_kernel<<<NBLK, TPB, SMEM_BYTES>>>(x, S, U, A, out);
}